// round 2
// baseline (speedup 1.0000x reference)
#include <cuda_runtime.h>
#include <math.h>

#define MAXN 1024
#define STRIDE 16

// Scratch (allocation-free rule: static __device__ globals)
__device__ float g_params[MAXN * STRIDE];   // unsorted per-gaussian params
__device__ float g_sorted[MAXN * STRIDE];   // depth-sorted (back-to-front)

// H/W/focal may arrive as int32 or float32 scalars; decide on device.
__device__ __forceinline__ float read_scalar(const void* p) {
    int v = *(const int*)p;
    if (v > 0 && v < 1000000) return (float)v;
    return __int_as_float(v);
}

// ---------------------------------------------------------------------------
// Kernel A: preprocess all gaussians + bitonic sort by depth (descending,
// index-ascending tiebreak == stable argsort(-depths)), gather sorted params.
// One block of MAXN threads.
// ---------------------------------------------------------------------------
__global__ __launch_bounds__(MAXN, 1)
void gs_prep_sort(const float* __restrict__ cam,
                  const float* __restrict__ means,
                  const float* __restrict__ scales,
                  const float* __restrict__ rots,
                  const float* __restrict__ cols,
                  const float* __restrict__ opacs,
                  const void* pH, const void* pW, const void* pF, int N)
{
    __shared__ float skey[MAXN];
    __shared__ int   sidx[MAXN];
    const int t = threadIdx.x;

    const float Hf = read_scalar(pH);
    const float Wf = read_scalar(pW);
    const float f  = read_scalar(pF);

    float depth = -1e30f;  // pads sort to the end (descending sort)

    if (t < N) {
        // camera
        float R00=cam[0], R01=cam[1], R02=cam[2],  T0=cam[3];
        float R10=cam[4], R11=cam[5], R12=cam[6],  T1=cam[7];
        float R20=cam[8], R21=cam[9], R22=cam[10], T2=cam[11];

        float m0=means[3*t], m1=means[3*t+1], m2=means[3*t+2];
        float mx = R00*m0 + R01*m1 + R02*m2 + T0;
        float my = R10*m0 + R11*m1 + R12*m2 + T1;
        float mz = R20*m0 + R21*m1 + R22*m2 + T2;
        depth = mz;
        float Z  = fmaxf(mz, 1e-10f);
        float cx = f*mx/Z + Wf*0.5f;
        float cy = f*my/Z + Hf*0.5f;

        // quaternion -> rotation
        float qw=rots[4*t], qx=rots[4*t+1], qy=rots[4*t+2], qz=rots[4*t+3];
        float qn = sqrtf(qw*qw + qx*qx + qy*qy + qz*qz);
        qw/=qn; qx/=qn; qy/=qn; qz/=qn;
        float G00=1.f-2.f*(qy*qy+qz*qz), G01=2.f*(qx*qy-qw*qz), G02=2.f*(qx*qz+qw*qy);
        float G10=2.f*(qx*qy+qw*qz), G11=1.f-2.f*(qx*qx+qz*qz), G12=2.f*(qy*qz-qw*qx);
        float G20=2.f*(qx*qz-qw*qy), G21=2.f*(qy*qz+qw*qx), G22=1.f-2.f*(qx*qx+qy*qy);

        float s0=scales[3*t], s1=scales[3*t+1], s2=scales[3*t+2];
        float v0=s0*s0, v1=s1*s1, v2=s2*s2;

        // cov3d = G diag(v) G^T (symmetric, 6 unique)
        float C00 = G00*G00*v0 + G01*G01*v1 + G02*G02*v2;
        float C01 = G00*G10*v0 + G01*G11*v1 + G02*G12*v2;
        float C02 = G00*G20*v0 + G01*G21*v1 + G02*G22*v2;
        float C11 = G10*G10*v0 + G11*G11*v1 + G12*G12*v2;
        float C12 = G10*G20*v0 + G11*G21*v1 + G12*G22*v2;
        float C22 = G20*G20*v0 + G21*G21*v1 + G22*G22*v2;

        // cov_cam = Rc C Rc^T ; V = Rc*C
        float V00 = R00*C00+R01*C01+R02*C02;
        float V01 = R00*C01+R01*C11+R02*C12;
        float V02 = R00*C02+R01*C12+R02*C22;
        float V10 = R10*C00+R11*C01+R12*C02;
        float V11 = R10*C01+R11*C11+R12*C12;
        float V12 = R10*C02+R11*C12+R12*C22;
        float V20 = R20*C00+R21*C01+R22*C02;
        float V21 = R20*C01+R21*C11+R22*C12;
        float V22 = R20*C02+R21*C12+R22*C22;
        float cc00 = V00*R00+V01*R01+V02*R02;
        float cc01 = V00*R10+V01*R11+V02*R12;
        float cc02 = V00*R20+V01*R21+V02*R22;
        float cc10 = V10*R00+V11*R01+V12*R02;
        float cc11 = V10*R10+V11*R11+V12*R12;
        float cc12 = V10*R20+V11*R21+V12*R22;
        float cc20 = V20*R00+V21*R01+V22*R02;
        float cc21 = V20*R10+V21*R11+V22*R12;
        float cc22 = V20*R20+V21*R21+V22*R22;

        // projection Jacobian (2x3, sparse)
        float j00 = f/Z,  j02 = -f*mx/(Z*Z);
        float j11 = f/Z,  j12 = -f*my/(Z*Z);

        // cov2d = J cov_cam J^T + 1e-6 I
        float u00 = j00*cc00 + j02*cc20;
        float u01 = j00*cc01 + j02*cc21;
        float u02 = j00*cc02 + j02*cc22;
        float u10 = j11*cc10 + j12*cc20;
        float u11 = j11*cc11 + j12*cc21;
        float u12 = j11*cc12 + j12*cc22;
        float a    = u00*j00 + u02*j02 + 1e-6f;
        float bb   = u01*j11 + u02*j12;   // cov2d[0][1]
        float cval = u10*j00 + u12*j02;   // cov2d[1][0]
        float d    = u11*j11 + u12*j12 + 1e-6f;

        float det = a*d - bb*cval;
        float inv = 1.0f/det;
        // wgt exponent: -0.5*(iA dx^2 + (iB+iC) dx dy + iD dy^2)
        float wA = -0.5f * d * inv;
        float wB =  0.5f * (bb + cval) * inv;
        float wD = -0.5f * a * inv;

        float radius = 3.0f * fmaxf(sqrtf(a + 1e-10f), sqrtf(d + 1e-10f));
        bool culled = (cx < -Wf*0.5f) || (cx > Wf*1.5f) || (cy < -Hf*0.5f) || (cy > Hf*1.5f);
        bool valid  = depth > 0.0f;
        float act   = (valid && !culled) ? 1.0f : 0.0f;

        float x0 = fmaxf(0.0f, truncf(cx - radius));
        float x1 = fminf(Wf,   truncf(cx + radius + 1.0f));
        float y0 = fmaxf(0.0f, truncf(cy - radius));
        float y1 = fminf(Hf,   truncf(cy + radius + 1.0f));

        float op = (1.0f / (1.0f + expf(-opacs[t]))) * act;

        float* g = &g_params[t*STRIDE];
        g[0]=cx;  g[1]=cy;  g[2]=wA;  g[3]=wB;  g[4]=wD;
        g[5]=x0;  g[6]=x1;  g[7]=y0;  g[8]=y1;  g[9]=op;
        g[10]=cols[3*t]; g[11]=cols[3*t+1]; g[12]=cols[3*t+2];
        g[13]=0.f; g[14]=0.f; g[15]=0.f;
    }

    skey[t] = depth;
    sidx[t] = t;
    __syncthreads();

    // Bitonic sort: descending depth, ascending original index on ties
    for (int k = 2; k <= MAXN; k <<= 1) {
        for (int j = k >> 1; j > 0; j >>= 1) {
            int ixj = t ^ j;
            if (ixj > t) {
                float ka = skey[t], kb = skey[ixj];
                int   ia = sidx[t], ib = sidx[ixj];
                // "t's element should precede ixj's element" in desired order
                bool ordered = (ka > kb) || (ka == kb && ia < ib);
                bool doswap = ((t & k) == 0) ? !ordered : ordered;
                if (doswap) {
                    skey[t] = kb; skey[ixj] = ka;
                    sidx[t] = ib; sidx[ixj] = ia;
                }
            }
            __syncthreads();
        }
    }

    // Gather into sorted array
    int src = sidx[t];
    float4* dst = (float4*)&g_sorted[t*STRIDE];
    if (src < N) {
        const float4* s = (const float4*)&g_params[src*STRIDE];
        dst[0]=s[0]; dst[1]=s[1]; dst[2]=s[2]; dst[3]=s[3];
    } else {
        float4 z = make_float4(0.f,0.f,0.f,0.f);
        dst[0]=z; dst[1]=z; dst[2]=z; dst[3]=z;  // op==0 -> never contributes
    }
}

// ---------------------------------------------------------------------------
// Kernel B: tile rasterizer. 16x16 tile per block (256 threads).
// Ordered ballot-compaction of tile-intersecting gaussians, then sequential
// alpha composite per pixel (skipping zero-weight gaussians is exact).
// ---------------------------------------------------------------------------
__global__ __launch_bounds__(256, 8)
void gs_rasterize(float* __restrict__ out, int N, int W, int H)
{
    const int tilesX = (W + 15) >> 4;
    const int tileX = blockIdx.x % tilesX;
    const int tileY = blockIdx.x / tilesX;
    const int lx = threadIdx.x & 15, ly = threadIdx.x >> 4;
    const int pxi = tileX*16 + lx, pyi = tileY*16 + ly;
    const float px = (float)pxi, py = (float)pyi;
    const float tx0 = (float)(tileX*16), ty0 = (float)(tileY*16);
    const float tx1 = tx0 + 16.0f,       ty1 = ty0 + 16.0f;

    __shared__ int   s_list[MAXN];
    __shared__ int   s_len;
    __shared__ int   s_wcnt[8];
    __shared__ int   s_woff[8];

    if (threadIdx.x == 0) s_len = 0;
    __syncthreads();

    const int lane = threadIdx.x & 31;
    const int wrp  = threadIdx.x >> 5;

    for (int base = 0; base < N; base += 256) {
        int gi = base + threadIdx.x;
        bool pred = false;
        if (gi < N) {
            const float* g = &g_sorted[gi*STRIDE];
            float x0=g[5], x1=g[6], y0=g[7], y1=g[8], op=g[9];
            pred = (op > 0.0f) && (x0 < tx1) && (x1 > tx0) && (y0 < ty1) && (y1 > ty0);
        }
        unsigned m = __ballot_sync(0xffffffffu, pred);
        if (lane == 0) s_wcnt[wrp] = __popc(m);
        __syncthreads();
        if (threadIdx.x == 0) {
            int s = s_len;
            #pragma unroll
            for (int w = 0; w < 8; w++) { s_woff[w] = s; s += s_wcnt[w]; }
            s_len = s;
        }
        __syncthreads();
        if (pred)
            s_list[s_woff[wrp] + __popc(m & ((1u << lane) - 1u))] = gi;
        __syncthreads();
    }

    const int n = s_len;
    float alpha = 0.f, cr = 0.f, cg = 0.f, cb = 0.f;

    for (int i = 0; i < n; i++) {
        const float* g = &g_sorted[s_list[i]*STRIDE];   // uniform -> L1 broadcast
        float cx=g[0], cy=g[1], wA=g[2], wB=g[3], wD=g[4];
        float x0=g[5], x1=g[6], y0=g[7], y1=g[8], op=g[9];
        float gr=g[10], gg=g[11], gb=g[12];

        float dx = px - cx, dy = py - cy;
        float e  = fmaf(wA*dx, dx, fmaf(wB*dx, dy, wD*dy*dy));
        bool inbox = (px >= x0) & (px < x1) & (py >= y0) & (py < y1);
        float w  = inbox ? __expf(e) * op : 0.0f;
        float wc = w * (1.0f - alpha);
        alpha += wc;
        cr = fmaf(gr, wc, cr);
        cg = fmaf(gg, wc, cg);
        cb = fmaf(gb, wc, cb);
    }

    if (pxi < W && pyi < H) {
        int o = (pyi*W + pxi)*3;
        out[o+0] = cr;
        out[o+1] = cg;
        out[o+2] = cb;
    }
}

// ---------------------------------------------------------------------------
extern "C" void kernel_launch(void* const* d_in, const int* in_sizes, int n_in,
                              void* d_out, int out_size)
{
    const float* cam    = (const float*)d_in[0];
    const float* means  = (const float*)d_in[1];
    const float* scales = (const float*)d_in[2];
    const float* rots   = (const float*)d_in[3];
    const float* cols   = (const float*)d_in[4];
    const float* opacs  = (const float*)d_in[5];
    const void*  pH     = d_in[6];
    const void*  pW     = d_in[7];
    const void*  pF     = d_in[8];
    float* out = (float*)d_out;

    int N = in_sizes[1] / 3;
    if (N > MAXN) N = MAXN;

    // assume square image: H*W = out_size/3
    int hw = out_size / 3;
    int side = 1;
    while ((long long)(side+1)*(side+1) <= hw) side++;
    int W = side, H = side;

    gs_prep_sort<<<1, MAXN>>>(cam, means, scales, rots, cols, opacs, pH, pW, pF, N);

    int tilesX = (W + 15) >> 4;
    int tilesY = (H + 15) >> 4;
    gs_rasterize<<<tilesX * tilesY, 256>>>(out, N, W, H);
}

// round 3
// speedup vs baseline: 1.6136x; 1.6136x over previous
#include <cuda_runtime.h>
#include <math.h>

#define MAXN   1024
#define STRIDE 16
#define CHUNK  128      // gaussians per depth-chunk in the rasterizer
#define MAXTILES 256    // supports up to 256x256 images

// Scratch (allocation-free rule: static __device__ globals)
__device__ float  g_sorted[MAXN * STRIDE];              // depth-sorted params
__device__ float4 g_partial[MAXTILES * 8 * 256];        // per (tile,chunk,pixel) partials

// H/W/focal may arrive as int32 or float32 scalars; decide on device.
__device__ __forceinline__ float read_scalar(const void* p) {
    int v = *(const int*)p;
    if (v > 0 && v < 1000000) return (float)v;
    return __int_as_float(v);
}

// ---------------------------------------------------------------------------
// Kernel 1: fused rank-sort + preprocess.
// Each block recomputes ALL depths (3 FMAs each) into smem, each thread
// rank-sorts its own gaussian by all-pairs comparison (stable descending ==
// argsort(-depths)), computes the full projection/covariance params, and
// scatters them directly to the sorted slot.
// ---------------------------------------------------------------------------
__global__ __launch_bounds__(256, 4)
void gs_prep(const float* __restrict__ cam,
             const float* __restrict__ means,
             const float* __restrict__ scales,
             const float* __restrict__ rots,
             const float* __restrict__ cols,
             const float* __restrict__ opacs,
             const void* pH, const void* pW, const void* pF, int N)
{
    __shared__ float sdep[MAXN];
    const int tid = threadIdx.x;
    const int t   = blockIdx.x * 256 + tid;

    const float Hf = read_scalar(pH);
    const float Wf = read_scalar(pW);
    const float f  = read_scalar(pF);

    // camera
    const float R00=cam[0], R01=cam[1], R02=cam[2],  T0=cam[3];
    const float R10=cam[4], R11=cam[5], R12=cam[6],  T1=cam[7];
    const float R20=cam[8], R21=cam[9], R22=cam[10], T2=cam[11];

    // all depths into smem (cheap: 3 FMA each)
    for (int j = tid; j < MAXN; j += 256) {
        float d = -1e30f;
        if (j < N)
            d = R20*means[3*j] + R21*means[3*j+1] + R22*means[3*j+2] + T2;
        sdep[j] = d;
    }
    __syncthreads();

    if (t >= N) return;

    // stable descending rank: count elements that precede t
    const float di = sdep[t];
    int rank = 0;
    const float4* s4 = (const float4*)sdep;
    #pragma unroll 8
    for (int q = 0; q < MAXN/4; q++) {
        float4 d4 = s4[q];
        int j = q * 4;
        rank += (d4.x > di) || (d4.x == di && (j+0) < t);
        rank += (d4.y > di) || (d4.y == di && (j+1) < t);
        rank += (d4.z > di) || (d4.z == di && (j+2) < t);
        rank += (d4.w > di) || (d4.w == di && (j+3) < t);
    }

    // ---- full per-gaussian math ----
    float m0=means[3*t], m1=means[3*t+1], m2=means[3*t+2];
    float mx = R00*m0 + R01*m1 + R02*m2 + T0;
    float my = R10*m0 + R11*m1 + R12*m2 + T1;
    float mz = di;                           // == R2.m + T2
    float Z  = fmaxf(mz, 1e-10f);
    float cx = f*mx/Z + Wf*0.5f;
    float cy = f*my/Z + Hf*0.5f;

    float qw=rots[4*t], qx=rots[4*t+1], qy=rots[4*t+2], qz=rots[4*t+3];
    float qn = sqrtf(qw*qw + qx*qx + qy*qy + qz*qz);
    qw/=qn; qx/=qn; qy/=qn; qz/=qn;
    float G00=1.f-2.f*(qy*qy+qz*qz), G01=2.f*(qx*qy-qw*qz), G02=2.f*(qx*qz+qw*qy);
    float G10=2.f*(qx*qy+qw*qz), G11=1.f-2.f*(qx*qx+qz*qz), G12=2.f*(qy*qz-qw*qx);
    float G20=2.f*(qx*qz-qw*qy), G21=2.f*(qy*qz+qw*qx), G22=1.f-2.f*(qx*qx+qy*qy);

    float s0=scales[3*t], s1=scales[3*t+1], s2=scales[3*t+2];
    float v0=s0*s0, v1=s1*s1, v2=s2*s2;

    float C00 = G00*G00*v0 + G01*G01*v1 + G02*G02*v2;
    float C01 = G00*G10*v0 + G01*G11*v1 + G02*G12*v2;
    float C02 = G00*G20*v0 + G01*G21*v1 + G02*G22*v2;
    float C11 = G10*G10*v0 + G11*G11*v1 + G12*G12*v2;
    float C12 = G10*G20*v0 + G11*G21*v1 + G12*G22*v2;
    float C22 = G20*G20*v0 + G21*G21*v1 + G22*G22*v2;

    float V00 = R00*C00+R01*C01+R02*C02;
    float V01 = R00*C01+R01*C11+R02*C12;
    float V02 = R00*C02+R01*C12+R02*C22;
    float V10 = R10*C00+R11*C01+R12*C02;
    float V11 = R10*C01+R11*C11+R12*C12;
    float V12 = R10*C02+R11*C12+R12*C22;
    float V20 = R20*C00+R21*C01+R22*C02;
    float V21 = R20*C01+R21*C11+R22*C12;
    float V22 = R20*C02+R21*C12+R22*C22;
    float cc00 = V00*R00+V01*R01+V02*R02;
    float cc01 = V00*R10+V01*R11+V02*R12;
    float cc02 = V00*R20+V01*R21+V02*R22;
    float cc10 = V10*R00+V11*R01+V12*R02;
    float cc11 = V10*R10+V11*R11+V12*R12;
    float cc12 = V10*R20+V11*R21+V12*R22;
    float cc20 = V20*R00+V21*R01+V22*R02;
    float cc21 = V20*R10+V21*R11+V22*R12;
    float cc22 = V20*R20+V21*R21+V22*R22;

    float j00 = f/Z,  j02 = -f*mx/(Z*Z);
    float j11 = f/Z,  j12 = -f*my/(Z*Z);

    float u00 = j00*cc00 + j02*cc20;
    float u01 = j00*cc01 + j02*cc21;
    float u02 = j00*cc02 + j02*cc22;
    float u10 = j11*cc10 + j12*cc20;
    float u11 = j11*cc11 + j12*cc21;
    float u12 = j11*cc12 + j12*cc22;
    float a    = u00*j00 + u02*j02 + 1e-6f;
    float bb   = u01*j11 + u02*j12;
    float cval = u10*j00 + u12*j02;
    float d    = u11*j11 + u12*j12 + 1e-6f;

    float det = a*d - bb*cval;
    float inv = 1.0f/det;
    float wA = -0.5f * d * inv;
    float wB =  0.5f * (bb + cval) * inv;
    float wD = -0.5f * a * inv;

    float radius = 3.0f * fmaxf(sqrtf(a + 1e-10f), sqrtf(d + 1e-10f));
    bool culled = (cx < -Wf*0.5f) || (cx > Wf*1.5f) || (cy < -Hf*0.5f) || (cy > Hf*1.5f);
    bool valid  = mz > 0.0f;
    float act   = (valid && !culled) ? 1.0f : 0.0f;

    float x0 = fmaxf(0.0f, truncf(cx - radius));
    float x1 = fminf(Wf,   truncf(cx + radius + 1.0f));
    float y0 = fmaxf(0.0f, truncf(cy - radius));
    float y1 = fminf(Hf,   truncf(cy + radius + 1.0f));

    float op = (1.0f / (1.0f + expf(-opacs[t]))) * act;

    float4* g = (float4*)&g_sorted[rank * STRIDE];
    g[0] = make_float4(cx, cy, wA, wB);
    g[1] = make_float4(wD, x0, x1, y0);
    g[2] = make_float4(y1, op, cols[3*t], cols[3*t+1]);
    g[3] = make_float4(cols[3*t+2], 0.f, 0.f, 0.f);
}

// ---------------------------------------------------------------------------
// Kernel 2: chunked tile rasterizer. grid = (tiles, K chunks), 256 threads.
// Each block compacts its CHUNK-slice of the sorted list against its 16x16
// tile (order-preserving ballot compaction), composites it, and writes a
// per-(tile,chunk) partial (alpha, rgb). The "over" operator is associative,
// so chunks can be merged in order afterwards.
// ---------------------------------------------------------------------------
__global__ __launch_bounds__(256, 8)
void gs_rasterize(int N, int W, int H, int K)
{
    const int tilesX = (W + 15) >> 4;
    const int tile  = blockIdx.x;
    const int chunk = blockIdx.y;
    const int tileX = tile % tilesX, tileY = tile / tilesX;
    const int tid = threadIdx.x;
    const int lx = tid & 15, ly = tid >> 4;
    const float px = (float)(tileX*16 + lx), py = (float)(tileY*16 + ly);
    const float tx0 = (float)(tileX*16), ty0 = (float)(tileY*16);
    const float tx1 = tx0 + 16.0f,       ty1 = ty0 + 16.0f;

    __shared__ int s_list[CHUNK];
    __shared__ int s_cnt[CHUNK/32];
    __shared__ int s_off[CHUNK/32];
    __shared__ int s_len;

    const int lane = tid & 31;
    const int wrp  = tid >> 5;

    // order-preserving compaction (warps 0..CHUNK/32-1, one ballot round)
    if (wrp < CHUNK/32) {
        int gi = chunk * CHUNK + tid;
        bool pred = false;
        if (gi < N) {
            const float* g = &g_sorted[gi*STRIDE];
            float x0=g[5], x1=g[6], y0=g[7], y1=g[8], op=g[9];
            pred = (op > 0.0f) && (x0 < tx1) && (x1 > tx0) && (y0 < ty1) && (y1 > ty0);
        }
        unsigned m = __ballot_sync(0xffffffffu, pred);
        if (lane == 0) s_cnt[wrp] = __popc(m);
        // offsets need all counts; do prefix after a barrier below
        if (pred) s_list[tid] = -1;  // placeholder to keep smem init cheap (overwritten)
        __syncwarp();
        // stash compaction info in registers
        if (pred) {
            // position within warp
            int pos = __popc(m & ((1u << lane) - 1u));
            // temporarily store (warp-local) — final index after prefix
            s_list[tid] = pos;  // reuse; resolved after prefix
        }
        // fallthrough to block barrier
        if (lane == 0 && wrp == 0) s_len = 0;
    }
    __syncthreads();
    if (tid == 0) {
        int s = 0;
        #pragma unroll
        for (int w = 0; w < CHUNK/32; w++) { s_off[w] = s; s += s_cnt[w]; }
        s_len = s;
    }
    __syncthreads();
    // scatter gaussian indices into final compacted order
    if (wrp < CHUNK/32) {
        int gi = chunk * CHUNK + tid;
        bool pred = false;
        if (gi < N) {
            const float* g = &g_sorted[gi*STRIDE];
            float x0=g[5], x1=g[6], y0=g[7], y1=g[8], op=g[9];
            pred = (op > 0.0f) && (x0 < tx1) && (x1 > tx0) && (y0 < ty1) && (y1 > ty0);
        }
        unsigned m = __ballot_sync(0xffffffffu, pred);
        if (pred) {
            int pos = s_off[wrp] + __popc(m & ((1u << lane) - 1u));
            s_list[pos] = gi;
        }
    }
    __syncthreads();

    const int n = s_len;
    float alpha = 0.f, cr = 0.f, cg = 0.f, cb = 0.f;

    for (int i = 0; i < n; i++) {
        const float* g = &g_sorted[s_list[i]*STRIDE];   // uniform -> broadcast
        float cx=g[0], cy=g[1], wA=g[2], wB=g[3], wD=g[4];
        float x0=g[5], x1=g[6], y0=g[7], y1=g[8], op=g[9];
        float gr=g[10], gg=g[11], gb=g[12];

        float dx = px - cx, dy = py - cy;
        float e  = fmaf(wA*dx, dx, fmaf(wB*dx, dy, wD*dy*dy));
        bool inbox = (px >= x0) & (px < x1) & (py >= y0) & (py < y1);
        float w  = inbox ? __expf(e) * op : 0.0f;
        float wc = w * (1.0f - alpha);
        alpha += wc;
        cr = fmaf(gr, wc, cr);
        cg = fmaf(gg, wc, cg);
        cb = fmaf(gb, wc, cb);
    }

    g_partial[(tile*K + chunk)*256 + tid] = make_float4(alpha, cr, cg, cb);
}

// ---------------------------------------------------------------------------
// Kernel 3: combine K depth-chunk partials per pixel, in order.
// ---------------------------------------------------------------------------
__global__ __launch_bounds__(256)
void gs_combine(float* __restrict__ out, int W, int H, int K)
{
    int p = blockIdx.x * 256 + threadIdx.x;
    if (p >= W*H) return;
    int px = p % W, py = p / W;
    int tilesX = (W + 15) >> 4;
    int tile = (py >> 4)*tilesX + (px >> 4);
    int pix  = ((py & 15) << 4) + (px & 15);

    float A = 0.f, R = 0.f, G = 0.f, B = 0.f;
    for (int c = 0; c < K; c++) {
        float4 v = g_partial[(tile*K + c)*256 + pix];
        float tfac = 1.0f - A;
        A = fmaf(v.x, tfac, A);
        R = fmaf(v.y, tfac, R);
        G = fmaf(v.z, tfac, G);
        B = fmaf(v.w, tfac, B);
    }
    out[p*3+0] = R;
    out[p*3+1] = G;
    out[p*3+2] = B;
}

// ---------------------------------------------------------------------------
extern "C" void kernel_launch(void* const* d_in, const int* in_sizes, int n_in,
                              void* d_out, int out_size)
{
    const float* cam    = (const float*)d_in[0];
    const float* means  = (const float*)d_in[1];
    const float* scales = (const float*)d_in[2];
    const float* rots   = (const float*)d_in[3];
    const float* cols   = (const float*)d_in[4];
    const float* opacs  = (const float*)d_in[5];
    const void*  pH     = d_in[6];
    const void*  pW     = d_in[7];
    const void*  pF     = d_in[8];
    float* out = (float*)d_out;

    int N = in_sizes[1] / 3;
    if (N > MAXN) N = MAXN;

    // assume square image: H*W = out_size/3
    int hw = out_size / 3;
    int side = 1;
    while ((long long)(side+1)*(side+1) <= hw) side++;
    int W = side, H = side;

    int K = (N + CHUNK - 1) / CHUNK;      // depth chunks (8 for N=1024)
    int tilesX = (W + 15) >> 4;
    int tilesY = (H + 15) >> 4;

    gs_prep<<<(N + 255)/256, 256>>>(cam, means, scales, rots, cols, opacs, pH, pW, pF, N);

    dim3 rgrid(tilesX * tilesY, K);
    gs_rasterize<<<rgrid, 256>>>(N, W, H, K);

    gs_combine<<<(H*W + 255)/256, 256>>>(out, W, H, K);
}

// round 4
// speedup vs baseline: 2.7477x; 1.7028x over previous
#include <cuda_runtime.h>
#include <math.h>

#define MAXN   1024
#define STRIDE 16
#define CHUNK  128      // gaussians per depth-chunk in the rasterizer
#define GPB    16       // gaussians per prep block (one warp each)
#define MAXTILES 256

// Scratch (allocation-free rule: static __device__ globals)
__device__ float  g_sorted[MAXN * STRIDE];          // depth-sorted params
__device__ float4 g_partial[MAXTILES * 8 * 256];    // (tile,chunk,pixel) partials

// H/W/focal may arrive as int32 or float32 scalars; decide on device.
__device__ __forceinline__ float read_scalar(const void* p) {
    int v = *(const int*)p;
    if (v > 0 && v < 1000000) return (float)v;
    return __int_as_float(v);
}

// ---------------------------------------------------------------------------
// Kernel 1: fused warp-parallel rank-sort + preprocess.
// Grid = ceil(N/GPB) blocks x 512 threads (16 warps).
// Phase 1: block recomputes all MAXN depths into smem (3 FMA each).
// Phase 2: warp w computes the stable descending rank of gaussian
//          blockIdx*GPB + w: each lane counts 32 compares (conflict-free
//          stride), one redux.add folds the rank.
// Phase 3: threads 0..GPB-1 run full projection math, scatter to rank slot.
// ---------------------------------------------------------------------------
__global__ __launch_bounds__(512, 2)
void gs_prep(const float* __restrict__ cam,
             const float* __restrict__ means,
             const float* __restrict__ scales,
             const float* __restrict__ rots,
             const float* __restrict__ cols,
             const float* __restrict__ opacs,
             const void* pH, const void* pW, const void* pF, int N)
{
    __shared__ float sdep[MAXN];
    __shared__ int   srank[GPB];

    const int tid  = threadIdx.x;
    const int lane = tid & 31;
    const int wrp  = tid >> 5;

    const float Hf = read_scalar(pH);
    const float Wf = read_scalar(pW);
    const float f  = read_scalar(pF);

    const float R00=cam[0], R01=cam[1], R02=cam[2],  T0=cam[3];
    const float R10=cam[4], R11=cam[5], R12=cam[6],  T1=cam[7];
    const float R20=cam[8], R21=cam[9], R22=cam[10], T2=cam[11];

    // Phase 1: all depths into smem (each thread 2 elements for MAXN=1024)
    #pragma unroll
    for (int j = tid; j < MAXN; j += 512) {
        float d = -1e30f;   // pads sort after all real gaussians
        if (j < N)
            d = R20*means[3*j] + R21*means[3*j+1] + R22*means[3*j+2] + T2;
        sdep[j] = d;
    }
    __syncthreads();

    // Phase 2: warp w ranks gaussian g (stable descending == argsort(-depths))
    const int g = blockIdx.x * GPB + wrp;
    if (g < N) {
        const float dg = sdep[g];
        int cnt = 0;
        #pragma unroll
        for (int k = 0; k < MAXN/32; k++) {
            int j = k*32 + lane;             // bank = lane: conflict-free
            float dj = sdep[j];
            cnt += (dj > dg) || (dj == dg && j < g);
        }
        int rank = __reduce_add_sync(0xffffffffu, cnt);
        if (lane == 0) srank[wrp] = rank;
    }
    __syncthreads();

    // Phase 3: threads 0..GPB-1 do the heavy per-gaussian math
    if (tid >= GPB) return;
    const int t = blockIdx.x * GPB + tid;
    if (t >= N) return;
    const int rank = srank[tid];

    float m0=means[3*t], m1=means[3*t+1], m2=means[3*t+2];
    float mx = R00*m0 + R01*m1 + R02*m2 + T0;
    float my = R10*m0 + R11*m1 + R12*m2 + T1;
    float mz = sdep[t];
    float Z  = fmaxf(mz, 1e-10f);
    float cx = f*mx/Z + Wf*0.5f;
    float cy = f*my/Z + Hf*0.5f;

    float qw=rots[4*t], qx=rots[4*t+1], qy=rots[4*t+2], qz=rots[4*t+3];
    float qn = sqrtf(qw*qw + qx*qx + qy*qy + qz*qz);
    qw/=qn; qx/=qn; qy/=qn; qz/=qn;
    float G00=1.f-2.f*(qy*qy+qz*qz), G01=2.f*(qx*qy-qw*qz), G02=2.f*(qx*qz+qw*qy);
    float G10=2.f*(qx*qy+qw*qz), G11=1.f-2.f*(qx*qx+qz*qz), G12=2.f*(qy*qz-qw*qx);
    float G20=2.f*(qx*qz-qw*qy), G21=2.f*(qy*qz+qw*qx), G22=1.f-2.f*(qx*qx+qy*qy);

    float s0=scales[3*t], s1=scales[3*t+1], s2=scales[3*t+2];
    float v0=s0*s0, v1=s1*s1, v2=s2*s2;

    float C00 = G00*G00*v0 + G01*G01*v1 + G02*G02*v2;
    float C01 = G00*G10*v0 + G01*G11*v1 + G02*G12*v2;
    float C02 = G00*G20*v0 + G01*G21*v1 + G02*G22*v2;
    float C11 = G10*G10*v0 + G11*G11*v1 + G12*G12*v2;
    float C12 = G10*G20*v0 + G11*G21*v1 + G12*G22*v2;
    float C22 = G20*G20*v0 + G21*G21*v1 + G22*G22*v2;

    float V00 = R00*C00+R01*C01+R02*C02;
    float V01 = R00*C01+R01*C11+R02*C12;
    float V02 = R00*C02+R01*C12+R02*C22;
    float V10 = R10*C00+R11*C01+R12*C02;
    float V11 = R10*C01+R11*C11+R12*C12;
    float V12 = R10*C02+R11*C12+R12*C22;
    float V20 = R20*C00+R21*C01+R22*C02;
    float V21 = R20*C01+R21*C11+R22*C12;
    float V22 = R20*C02+R21*C12+R22*C22;
    float cc00 = V00*R00+V01*R01+V02*R02;
    float cc01 = V00*R10+V01*R11+V02*R12;
    float cc02 = V00*R20+V01*R21+V02*R22;
    float cc10 = V10*R00+V11*R01+V12*R02;
    float cc11 = V10*R10+V11*R11+V12*R12;
    float cc12 = V10*R20+V11*R21+V12*R22;
    float cc20 = V20*R00+V21*R01+V22*R02;
    float cc21 = V20*R10+V21*R11+V22*R12;
    float cc22 = V20*R20+V21*R21+V22*R22;

    float j00 = f/Z,  j02 = -f*mx/(Z*Z);
    float j11 = f/Z,  j12 = -f*my/(Z*Z);

    float u00 = j00*cc00 + j02*cc20;
    float u01 = j00*cc01 + j02*cc21;
    float u02 = j00*cc02 + j02*cc22;
    float u10 = j11*cc10 + j12*cc20;
    float u11 = j11*cc11 + j12*cc21;
    float u12 = j11*cc12 + j12*cc22;
    float a    = u00*j00 + u02*j02 + 1e-6f;
    float bb   = u01*j11 + u02*j12;
    float cval = u10*j00 + u12*j02;
    float d    = u11*j11 + u12*j12 + 1e-6f;

    float det = a*d - bb*cval;
    float inv = 1.0f/det;
    float wA = -0.5f * d * inv;
    float wB =  0.5f * (bb + cval) * inv;
    float wD = -0.5f * a * inv;

    float radius = 3.0f * fmaxf(sqrtf(a + 1e-10f), sqrtf(d + 1e-10f));
    bool culled = (cx < -Wf*0.5f) || (cx > Wf*1.5f) || (cy < -Hf*0.5f) || (cy > Hf*1.5f);
    bool valid  = mz > 0.0f;
    float act   = (valid && !culled) ? 1.0f : 0.0f;

    float x0 = fmaxf(0.0f, truncf(cx - radius));
    float x1 = fminf(Wf,   truncf(cx + radius + 1.0f));
    float y0 = fmaxf(0.0f, truncf(cy - radius));
    float y1 = fminf(Hf,   truncf(cy + radius + 1.0f));

    float op = (1.0f / (1.0f + expf(-opacs[t]))) * act;

    float4* gp = (float4*)&g_sorted[rank * STRIDE];
    gp[0] = make_float4(cx, cy, wA, wB);
    gp[1] = make_float4(wD, x0, x1, y0);
    gp[2] = make_float4(y1, op, cols[3*t], cols[3*t+1]);
    gp[3] = make_float4(cols[3*t+2], 0.f, 0.f, 0.f);
}

// ---------------------------------------------------------------------------
// Kernel 2: chunked tile rasterizer. grid = (tiles, K chunks), 256 threads.
// Order-preserving ballot compaction of this chunk's slice vs the tile bbox,
// then sequential alpha composite; writes per-(tile,chunk) partial.
// ---------------------------------------------------------------------------
__global__ __launch_bounds__(256, 8)
void gs_rasterize(int N, int W, int H, int K)
{
    const int tilesX = (W + 15) >> 4;
    const int tile  = blockIdx.x;
    const int chunk = blockIdx.y;
    const int tileX = tile % tilesX, tileY = tile / tilesX;
    const int tid = threadIdx.x;
    const int lx = tid & 15, ly = tid >> 4;
    const float px = (float)(tileX*16 + lx), py = (float)(tileY*16 + ly);
    const float tx0 = (float)(tileX*16), ty0 = (float)(tileY*16);
    const float tx1 = tx0 + 16.0f,       ty1 = ty0 + 16.0f;

    __shared__ int s_list[CHUNK];
    __shared__ int s_cnt[CHUNK/32];
    __shared__ int s_off[CHUNK/32];
    __shared__ int s_len;

    const int lane = tid & 31;
    const int wrp  = tid >> 5;

    // single-pass order-preserving compaction (pred/mask persist in regs)
    bool pred = false;
    int  gi   = chunk * CHUNK + tid;
    if (tid < CHUNK && gi < N) {
        const float* g = &g_sorted[gi*STRIDE];
        float x0=g[5], x1=g[6], y0=g[7], y1=g[8], op=g[9];
        pred = (op > 0.0f) && (x0 < tx1) && (x1 > tx0) && (y0 < ty1) && (y1 > ty0);
    }
    unsigned m = __ballot_sync(0xffffffffu, pred);
    if (lane == 0 && wrp < CHUNK/32) s_cnt[wrp] = __popc(m);
    __syncthreads();
    if (tid == 0) {
        int s = 0;
        #pragma unroll
        for (int w = 0; w < CHUNK/32; w++) { s_off[w] = s; s += s_cnt[w]; }
        s_len = s;
    }
    __syncthreads();
    if (pred)
        s_list[s_off[wrp] + __popc(m & ((1u << lane) - 1u))] = gi;
    __syncthreads();

    const int n = s_len;
    float alpha = 0.f, cr = 0.f, cg = 0.f, cb = 0.f;

    for (int i = 0; i < n; i++) {
        const float* g = &g_sorted[s_list[i]*STRIDE];   // uniform -> broadcast
        float cx=g[0], cy=g[1], wA=g[2], wB=g[3], wD=g[4];
        float x0=g[5], x1=g[6], y0=g[7], y1=g[8], op=g[9];
        float gr=g[10], gg=g[11], gb=g[12];

        float dx = px - cx, dy = py - cy;
        float e  = fmaf(wA*dx, dx, fmaf(wB*dx, dy, wD*dy*dy));
        bool inbox = (px >= x0) & (px < x1) & (py >= y0) & (py < y1);
        float w  = inbox ? __expf(e) * op : 0.0f;
        float wc = w * (1.0f - alpha);
        alpha += wc;
        cr = fmaf(gr, wc, cr);
        cg = fmaf(gg, wc, cg);
        cb = fmaf(gb, wc, cb);
    }

    g_partial[(tile*K + chunk)*256 + tid] = make_float4(alpha, cr, cg, cb);
}

// ---------------------------------------------------------------------------
// Kernel 3: combine K depth-chunk partials per pixel, in order.
// ---------------------------------------------------------------------------
__global__ __launch_bounds__(256)
void gs_combine(float* __restrict__ out, int W, int H, int K)
{
    int p = blockIdx.x * 256 + threadIdx.x;
    if (p >= W*H) return;
    int px = p % W, py = p / W;
    int tilesX = (W + 15) >> 4;
    int tile = (py >> 4)*tilesX + (px >> 4);
    int pix  = ((py & 15) << 4) + (px & 15);

    float A = 0.f, R = 0.f, G = 0.f, B = 0.f;
    for (int c = 0; c < K; c++) {
        float4 v = g_partial[(tile*K + c)*256 + pix];
        float tfac = 1.0f - A;
        A = fmaf(v.x, tfac, A);
        R = fmaf(v.y, tfac, R);
        G = fmaf(v.z, tfac, G);
        B = fmaf(v.w, tfac, B);
    }
    out[p*3+0] = R;
    out[p*3+1] = G;
    out[p*3+2] = B;
}

// ---------------------------------------------------------------------------
extern "C" void kernel_launch(void* const* d_in, const int* in_sizes, int n_in,
                              void* d_out, int out_size)
{
    const float* cam    = (const float*)d_in[0];
    const float* means  = (const float*)d_in[1];
    const float* scales = (const float*)d_in[2];
    const float* rots   = (const float*)d_in[3];
    const float* cols   = (const float*)d_in[4];
    const float* opacs  = (const float*)d_in[5];
    const void*  pH     = d_in[6];
    const void*  pW     = d_in[7];
    const void*  pF     = d_in[8];
    float* out = (float*)d_out;

    int N = in_sizes[1] / 3;
    if (N > MAXN) N = MAXN;

    // assume square image: H*W = out_size/3
    int hw = out_size / 3;
    int side = 1;
    while ((long long)(side+1)*(side+1) <= hw) side++;
    int W = side, H = side;

    int K = (N + CHUNK - 1) / CHUNK;      // depth chunks (8 for N=1024)
    int tilesX = (W + 15) >> 4;
    int tilesY = (H + 15) >> 4;

    gs_prep<<<(N + GPB - 1)/GPB, 512>>>(cam, means, scales, rots, cols, opacs, pH, pW, pF, N);

    dim3 rgrid(tilesX * tilesY, K);
    gs_rasterize<<<rgrid, 256>>>(N, W, H, K);

    gs_combine<<<(H*W + 255)/256, 256>>>(out, W, H, K);
}